// round 5
// baseline (speedup 1.0000x reference)
#include <cuda_runtime.h>
#include <math.h>

// x: (8,4096,512) -> N=32768, D=512 ; embed: (1,8192,512) -> C=8192
// Outputs (float32, concatenated in d_out):
//   quantize 16,777,216 | embed_ind 32,768 | new_embed 4,194,304 | new_cs 8,192

#define N_TOK   32768
#define C_CODES 8192
#define D_DIM   512
#define ONE_MINUS_DECAY 0.2f

// -------- device scratch ----------------------------------------------------
__device__ float g_embed_n[C_CODES * D_DIM];   // normalized codebook (16 MB)
__device__ float g_xn[N_TOK * D_DIM];          // normalized tokens   (64 MB)
__device__ float g_embed_sum[C_CODES * D_DIM]; // EMA numerator scatter
__device__ float g_bins[C_CODES];
__device__ int   g_ind[N_TOK];

// -------- helpers -----------------------------------------------------------
__device__ __forceinline__ float block_reduce_sum_128(float v) {
    #pragma unroll
    for (int o = 16; o > 0; o >>= 1) v += __shfl_xor_sync(0xffffffffu, v, o);
    __shared__ float sp[4];
    int w = threadIdx.x >> 5, l = threadIdx.x & 31;
    if (l == 0) sp[w] = v;
    __syncthreads();
    if (threadIdx.x == 0) sp[0] = sp[0] + sp[1] + sp[2] + sp[3];
    __syncthreads();
    return sp[0];
}

// Mimic XLA:CPU (LLVM aarch64, VF=4 IC=2) row reduction of squares:
//   p_l = sum_j fma(e[8j+l], e[8j+l], p_l)  (l = 0..7, j sequential)
//   lanewise v_l = p_l + p_{l+4}; tree: (v0+v2) + (v1+v3)
// Executed serially by one thread from smem (512 fmaf, 8 interleaved chains).
__device__ __forceinline__ float mimic_sumsq_512(const float* __restrict__ s) {
    float p0 = 0.f, p1 = 0.f, p2 = 0.f, p3 = 0.f;
    float p4 = 0.f, p5 = 0.f, p6 = 0.f, p7 = 0.f;
    #pragma unroll 4
    for (int j = 0; j < D_DIM; j += 8) {
        p0 = fmaf(s[j + 0], s[j + 0], p0);
        p1 = fmaf(s[j + 1], s[j + 1], p1);
        p2 = fmaf(s[j + 2], s[j + 2], p2);
        p3 = fmaf(s[j + 3], s[j + 3], p3);
        p4 = fmaf(s[j + 4], s[j + 4], p4);
        p5 = fmaf(s[j + 5], s[j + 5], p5);
        p6 = fmaf(s[j + 6], s[j + 6], p6);
        p7 = fmaf(s[j + 7], s[j + 7], p7);
    }
    float v0 = p0 + p4, v1 = p1 + p5, v2 = p2 + p6, v3 = p3 + p7;
    return (v0 + v2) + (v1 + v3);
}

// ============================================================================
// Kernel 1: normalize codebook rows (reference-faithful: sqrt(sumsq), clip,
// then IEEE fp32 DIVISION per element). Also zero scatter buffers.
// One block (128 threads) per code.
// ============================================================================
__global__ void norm_embed_kernel(const float* __restrict__ embed) {
    __shared__ float srow[D_DIM];
    __shared__ float s_norm;
    int c = blockIdx.x;
    int t = threadIdx.x;
    float4 e = reinterpret_cast<const float4*>(embed + (size_t)c * D_DIM)[t];
    reinterpret_cast<float4*>(srow)[t] = e;
    __syncthreads();
    if (t == 0) {
        float nrm = sqrtf(mimic_sumsq_512(srow));
        if (nrm < 1e-12f) nrm = 1e-12f;
        s_norm = nrm;
    }
    __syncthreads();
    float nrm = s_norm;
    float4 en = make_float4(__fdiv_rn(e.x, nrm), __fdiv_rn(e.y, nrm),
                            __fdiv_rn(e.z, nrm), __fdiv_rn(e.w, nrm));
    reinterpret_cast<float4*>(g_embed_n + (size_t)c * D_DIM)[t] = en;
    reinterpret_cast<float4*>(g_embed_sum + (size_t)c * D_DIM)[t] =
        make_float4(0.f, 0.f, 0.f, 0.f);
    if (t == 0) g_bins[c] = 0.f;
}

// ============================================================================
// Kernel 1b: normalize tokens (same reference-faithful arithmetic).
// ============================================================================
__global__ void norm_x_kernel(const float* __restrict__ X) {
    __shared__ float srow[D_DIM];
    __shared__ float s_norm;
    int n = blockIdx.x;
    int t = threadIdx.x;
    float4 xv = reinterpret_cast<const float4*>(X + (size_t)n * D_DIM)[t];
    reinterpret_cast<float4*>(srow)[t] = xv;
    __syncthreads();
    if (t == 0) {
        float nrm = sqrtf(mimic_sumsq_512(srow));
        if (nrm < 1e-12f) nrm = 1e-12f;
        s_norm = nrm;
    }
    __syncthreads();
    float nrm = s_norm;
    reinterpret_cast<float4*>(g_xn + (size_t)n * D_DIM)[t] =
        make_float4(__fdiv_rn(xv.x, nrm), __fdiv_rn(xv.y, nrm),
                    __fdiv_rn(xv.z, nrm), __fdiv_rn(xv.w, nrm));
}

// ============================================================================
// Kernel 2: fused fp32 GEMM + row argmax on normalized operands.
// Sequential-k single-accumulator fmaf per output element (matches Eigen /
// cuBLAS SGEMM accumulation order). BM=BN=128, BK=16, 256 thr, 8x8 microtile.
// ============================================================================
#define BM 128
#define BN 128
#define BK 16

__global__ __launch_bounds__(256, 2)
void argmax_kernel() {
    __shared__ float As[BK][BM];
    __shared__ float Bs[BK][BN];
    __shared__ float s_val[BM][16];
    __shared__ int   s_idx[BM][16];

    const int tid  = threadIdx.x;
    const int tcol = tid & 15;
    const int trow = tid >> 4;
    const int m0 = trow * 8;
    const int n0 = tcol * 8;
    const int rowBase = blockIdx.x * BM;
    const float* __restrict__ XN = g_xn;
    const float* __restrict__ EN = g_embed_n;

    const int lr = tid >> 2;
    const int lc = (tid & 3) * 4;

    float bestv[8];
    int   besti[8];
    #pragma unroll
    for (int i = 0; i < 8; i++) { bestv[i] = -3.4e38f; besti[i] = 0; }

    for (int nt = 0; nt < C_CODES / BN; nt++) {
        const int colBase = nt * BN;
        float acc[8][8];
        #pragma unroll
        for (int i = 0; i < 8; i++)
            #pragma unroll
            for (int j = 0; j < 8; j++) acc[i][j] = 0.f;

        for (int kt = 0; kt < D_DIM / BK; kt++) {
            const int k0 = kt * BK;
            {
                const float* p0 = XN + (size_t)(rowBase + lr) * D_DIM + k0 + lc;
                const float* p1 = p0 + (size_t)64 * D_DIM;
                float4 a0 = *reinterpret_cast<const float4*>(p0);
                float4 a1 = *reinterpret_cast<const float4*>(p1);
                As[lc + 0][lr] = a0.x; As[lc + 1][lr] = a0.y;
                As[lc + 2][lr] = a0.z; As[lc + 3][lr] = a0.w;
                As[lc + 0][lr + 64] = a1.x; As[lc + 1][lr + 64] = a1.y;
                As[lc + 2][lr + 64] = a1.z; As[lc + 3][lr + 64] = a1.w;
            }
            {
                const float* p0 = EN + (size_t)(colBase + lr) * D_DIM + k0 + lc;
                const float* p1 = p0 + (size_t)64 * D_DIM;
                float4 b0 = *reinterpret_cast<const float4*>(p0);
                float4 b1 = *reinterpret_cast<const float4*>(p1);
                Bs[lc + 0][lr] = b0.x; Bs[lc + 1][lr] = b0.y;
                Bs[lc + 2][lr] = b0.z; Bs[lc + 3][lr] = b0.w;
                Bs[lc + 0][lr + 64] = b1.x; Bs[lc + 1][lr + 64] = b1.y;
                Bs[lc + 2][lr + 64] = b1.z; Bs[lc + 3][lr + 64] = b1.w;
            }
            __syncthreads();

            #pragma unroll
            for (int k = 0; k < BK; k++) {
                float4 a0 = *reinterpret_cast<const float4*>(&As[k][m0]);
                float4 a1 = *reinterpret_cast<const float4*>(&As[k][m0 + 4]);
                float4 b0 = *reinterpret_cast<const float4*>(&Bs[k][n0]);
                float4 b1 = *reinterpret_cast<const float4*>(&Bs[k][n0 + 4]);
                float a[8] = {a0.x, a0.y, a0.z, a0.w, a1.x, a1.y, a1.z, a1.w};
                float b[8] = {b0.x, b0.y, b0.z, b0.w, b1.x, b1.y, b1.z, b1.w};
                #pragma unroll
                for (int i = 0; i < 8; i++)
                    #pragma unroll
                    for (int j = 0; j < 8; j++)
                        acc[i][j] = fmaf(a[i], b[j], acc[i][j]);
            }
            __syncthreads();
        }

        // fold tile into running best (j ascending -> first-index on exact tie,
        // matching jnp.argmax first-occurrence)
        #pragma unroll
        for (int j = 0; j < 8; j++) {
            const int c = colBase + n0 + j;
            #pragma unroll
            for (int i = 0; i < 8; i++) {
                if (acc[i][j] > bestv[i]) { bestv[i] = acc[i][j]; besti[i] = c; }
            }
        }
    }

    #pragma unroll
    for (int i = 0; i < 8; i++) {
        s_val[m0 + i][tcol] = bestv[i];
        s_idx[m0 + i][tcol] = besti[i];
    }
    __syncthreads();
    if (tid < BM) {
        float bv = -3.4e38f; int bi = 0x7fffffff;
        #pragma unroll
        for (int t = 0; t < 16; t++) {
            float v  = s_val[tid][t];
            int   ix = s_idx[tid][t];
            if (v > bv || (v == bv && ix < bi)) { bv = v; bi = ix; }
        }
        g_ind[rowBase + tid] = bi;
    }
}

// ============================================================================
// Kernel 3: per-token epilogue (gather quantize, scatter normalized x + bins).
// ============================================================================
__global__ void epilogue_kernel(const float* __restrict__ embed,
                                float* __restrict__ out_q,
                                float* __restrict__ out_ind) {
    int n = blockIdx.x;
    int t = threadIdx.x;
    int c = g_ind[n];

    float4 xn = reinterpret_cast<const float4*>(g_xn + (size_t)n * D_DIM)[t];
    float* es = g_embed_sum + (size_t)c * D_DIM + t * 4;
    atomicAdd(es + 0, xn.x);
    atomicAdd(es + 1, xn.y);
    atomicAdd(es + 2, xn.z);
    atomicAdd(es + 3, xn.w);

    float4 ev = reinterpret_cast<const float4*>(embed + (size_t)c * D_DIM)[t];
    reinterpret_cast<float4*>(out_q + (size_t)n * D_DIM)[t] = ev;

    if (t == 0) {
        out_ind[n] = (float)c;
        atomicAdd(&g_bins[c], 1.0f);
    }
}

// ============================================================================
// Kernel 4: per-code EMA finalize.
// ============================================================================
__global__ void finalize_kernel(const float* __restrict__ embed,
                                const float* __restrict__ cluster_size,
                                float* __restrict__ out_embed,
                                float* __restrict__ out_cs) {
    int c = blockIdx.x;
    int t = threadIdx.x;
    float b = g_bins[c];
    bool zero = (b == 0.0f);
    float inv_b = 1.0f / (zero ? 1.0f : b);

    float4 es = reinterpret_cast<const float4*>(g_embed_sum + (size_t)c * D_DIM)[t];
    float4 v = make_float4(es.x * inv_b, es.y * inv_b, es.z * inv_b, es.w * inv_b);
    float ss = v.x * v.x + v.y * v.y + v.z * v.z + v.w * v.w;
    ss = block_reduce_sum_128(ss);
    float rn = 1.0f / fmaxf(sqrtf(ss), 1e-12f);

    float4 en;
    if (zero) en = reinterpret_cast<const float4*>(g_embed_n + (size_t)c * D_DIM)[t];
    else      en = make_float4(v.x * rn, v.y * rn, v.z * rn, v.w * rn);

    float4 e = reinterpret_cast<const float4*>(embed + (size_t)c * D_DIM)[t];
    reinterpret_cast<float4*>(out_embed + (size_t)c * D_DIM)[t] =
        make_float4(e.x + ONE_MINUS_DECAY * (en.x - e.x),
                    e.y + ONE_MINUS_DECAY * (en.y - e.y),
                    e.z + ONE_MINUS_DECAY * (en.z - e.z),
                    e.w + ONE_MINUS_DECAY * (en.w - e.w));

    if (t == 0) {
        float cs = cluster_size[c];
        out_cs[c] = cs + ONE_MINUS_DECAY * (b - cs);
    }
}

// ============================================================================
extern "C" void kernel_launch(void* const* d_in, const int* in_sizes, int n_in,
                              void* d_out, int out_size) {
    const float* x     = (const float*)d_in[0];
    const float* embed = (const float*)d_in[1];
    const float* cs    = (const float*)d_in[2];

    float* out       = (float*)d_out;
    float* out_q     = out;
    float* out_ind   = out + 16777216;
    float* out_embed = out + 16777216 + 32768;
    float* out_cs    = out + 16777216 + 32768 + 4194304;

    norm_embed_kernel<<<C_CODES, 128>>>(embed);
    norm_x_kernel<<<N_TOK, 128>>>(x);
    argmax_kernel<<<N_TOK / BM, 256>>>();
    epilogue_kernel<<<N_TOK, 128>>>(embed, out_q, out_ind);
    finalize_kernel<<<C_CODES, 128>>>(embed, cs, out_embed, out_cs);
}